// round 8
// baseline (speedup 1.0000x reference)
#include <cuda_runtime.h>
#include <cuda_fp16.h>
#include <cstdint>

// ---------------------------------------------------------------------------
// WideHyperBasicBlock via mma.sync (HMMA). conv3x3 = 9 shifted GEMMs,
// fp16 in / fp32 accum. act padded [b][c][66][72] fp16, 3 x-shifted copies.
// weights: one-time relayout to [k][co][ci] fp32, per-sample combine to fp16.
// Conv CTA: 128co x 128px (2 rows), 256 thr, 8 warps, warp = 64co x 32px.
// Merged-ky stages: 12 stages (3 kx x 4 ci-chunks); each stage = A for 3
// ky-taps (48KB) + 4-row B window (32KB). 2 buffers x 80KB, dual sync.
// Epilogue via SMEM transpose -> coalesced uint4/float4 stores.
// ---------------------------------------------------------------------------

#define NB 32
#define NC 256
#define PROW 66
#define PCOLS 72
#define PSZ (NB * NC * PROW * PCOLS)
#define GWSZ (NB * 9 * NC * NC)
#define WSZ (9 * NC * NC)

__device__ __half g_actp1[3][PSZ];
__device__ __half g_actp2[3][PSZ];
__device__ __half g_gw1[GWSZ];
__device__ __half g_gw2[GWSZ];
__device__ float  g_wt1[WSZ], g_bt1[WSZ], g_wt2[WSZ], g_bt2[WSZ];

__device__ __forceinline__ uint32_t smem_u32(const void* p) {
    uint32_t a;
    asm("{ .reg .u64 t; cvta.to.shared.u64 t, %1; cvt.u32.u64 %0, t; }"
        : "=r"(a) : "l"(p));
    return a;
}
#define SWZ(o) ((o) ^ (((o) >> 3) & 0x70))
#define CPA16(dst, src) \
    asm volatile("cp.async.cg.shared.global [%0], [%1], 16;" :: "r"(dst), "l"(src) : "memory")

__device__ __forceinline__ uint4 pack8h(const __half* h) {
    union { uint4 u; __half2 h2[4]; } r;
    r.h2[0] = __halves2half2(h[0], h[1]);
    r.h2[1] = __halves2half2(h[2], h[3]);
    r.h2[2] = __halves2half2(h[4], h[5]);
    r.h2[3] = __halves2half2(h[6], h[7]);
    return r.u;
}

// --------------------------- aux kernels -----------------------------------
__global__ void zero_borders(__half* buf) {
    int t = blockIdx.x * blockDim.x + threadIdx.x;
    if (t >= 3 * NB * NC) return;
    int copy = t / (NB * NC);
    int bc   = t % (NB * NC);
    __half* base = buf + (size_t)copy * PSZ + (size_t)bc * PROW * PCOLS;
    uint4 z = {0, 0, 0, 0};
#pragma unroll
    for (int g = 0; g < 9; g++) {
        ((uint4*)(base))[g] = z;
        ((uint4*)(base + 65 * PCOLS))[g] = z;
    }
    __half hz = __float2half(0.0f);
    if (copy == 0) for (int r = 1; r < 65; r++) base[r * PCOLS] = hz;
    if (copy == 2) for (int r = 1; r < 65; r++) base[r * PCOLS + 63] = hz;
}

// one-time gather: w[(co*256+ci)*9+k] -> wt [k][co][ci] fp32 (and bias)
__global__ void wprep(const float* __restrict__ w, const float* __restrict__ bw,
                      float* __restrict__ wt, float* __restrict__ bt) {
    int gid = blockIdx.x * blockDim.x + threadIdx.x;
    if (gid >= WSZ) return;
    int k = gid >> 16;
    int m = gid & 0xFFFF;
    int src = m * 9 + k;
    wt[gid] = w[src];
    bt[gid] = bw[src];
}

// per-sample combine: gw[b][k][co][ci] = fp16(h_b * wt + bt), x8 vectorized
__global__ void wcombine(const float* __restrict__ wt, const float* __restrict__ bt,
                         const float* __restrict__ hv, __half* __restrict__ gw) {
    int gid = blockIdx.x * blockDim.x + threadIdx.x;
    int idx = gid * 8;                                  // [b][k][co][ci]
    int bk = idx >> 16;
    int k = bk % 9, b = bk / 9;
    int m = idx & 0xFFFF;
    float h = 0.5f + hv[b] * (1.0f / 64.0f);
    const float4* W = (const float4*)(wt + (k << 16) + m);
    const float4* Bv = (const float4*)(bt + (k << 16) + m);
    float4 w0 = W[0], w1 = W[1], b0 = Bv[0], b1 = Bv[1];
    __half hh[8];
    hh[0] = __float2half(fmaf(h, w0.x, b0.x));
    hh[1] = __float2half(fmaf(h, w0.y, b0.y));
    hh[2] = __float2half(fmaf(h, w0.z, b0.z));
    hh[3] = __float2half(fmaf(h, w0.w, b0.w));
    hh[4] = __float2half(fmaf(h, w1.x, b1.x));
    hh[5] = __float2half(fmaf(h, w1.y, b1.y));
    hh[6] = __float2half(fmaf(h, w1.z, b1.z));
    hh[7] = __float2half(fmaf(h, w1.w, b1.w));
    *(uint4*)(gw + idx) = pack8h(hh);
}

// bn+relu+pad, 8 px per thread, all three copies via aligned uint4 stores
__global__ void bn_relu_pad(const float* __restrict__ x,
                            const float* __restrict__ g, const float* __restrict__ be,
                            const float* __restrict__ m, const float* __restrict__ v,
                            __half* __restrict__ a0, __half* __restrict__ a1,
                            __half* __restrict__ a2) {
    int gid = blockIdx.x * blockDim.x + threadIdx.x;    // [b][c][yy][xc]
    int xc = gid & 7, yy = (gid >> 3) & 63, c = (gid >> 9) & 255, b = gid >> 17;
    float inv  = g[c] * rsqrtf(v[c] + 1e-5f);
    float bias = be[c] - m[c] * inv;
    const float* xp = x + (((size_t)(b * 256 + c)) << 12) + (yy << 6) + xc * 8;
    float4 va = *(const float4*)xp;
    float4 vb = *(const float4*)(xp + 4);
    float vv[10];
    vv[0] = (xc == 0) ? 0.0f : xp[-1];
    vv[1] = va.x; vv[2] = va.y; vv[3] = va.z; vv[4] = va.w;
    vv[5] = vb.x; vv[6] = vb.y; vv[7] = vb.z; vv[8] = vb.w;
    vv[9] = (xc == 7) ? 0.0f : xp[8];
    __half hh[10];
#pragma unroll
    for (int t = 0; t < 10; t++)
        hh[t] = __float2half(fmaxf(fmaf(vv[t], inv, bias), 0.0f));
    if (xc == 0) hh[0] = __float2half(0.0f);
    if (xc == 7) hh[9] = __float2half(0.0f);
    int rb = ((b * 256 + c) * PROW + yy + 1) * PCOLS + xc * 8;
    *(uint4*)(a1 + rb) = pack8h(hh + 1);
    *(uint4*)(a0 + rb) = pack8h(hh + 0);
    *(uint4*)(a2 + rb) = pack8h(hh + 2);
}

// --------------------------- main conv kernel ------------------------------
// Stage layout (per 80KB buffer):
//   A[ky][128co][64ci] fp16 SW128 : ky*16384, ky=0..2  (48KB)
//   B[j][64ci][64px]  fp16 SW128 : 49152 + j*8192, j=0..3 (padded rows y0+j)
#define STAGE_BYTES 81920
#define SMEM_BYTES  (2 * STAGE_BYTES)

template <int MODE>
__global__ __launch_bounds__(256)
void conv_mma(const __half* __restrict__ ap0, const __half* __restrict__ ap1,
              const __half* __restrict__ ap2, const __half* __restrict__ gw,
              const float* __restrict__ bn_g, const float* __restrict__ bn_b,
              const float* __restrict__ bn_m, const float* __restrict__ bn_v,
              const float* __restrict__ xres,
              __half* __restrict__ o0, __half* __restrict__ o1, __half* __restrict__ o2,
              float* __restrict__ out)
{
    extern __shared__ __align__(1024) char smem[];
    const uint32_t sb = smem_u32(smem);
    const int tid  = threadIdx.x;
    const int wid  = tid >> 5, lane = tid & 31;
    const int wm   = wid & 1;          // co half (64 co)
    const int wn   = wid >> 1;         // 0..3: 32-px strip
    const int jblk = wn >> 1;          // output row within tile (0/1)
    const int nbase = (wn & 1) * 32;

    const int y0  = blockIdx.x * 2;
    const int co0 = blockIdx.y * 128;
    const int b   = blockIdx.z;

    const int lr  = lane & 15;
    const int lhi = (lane >> 4) & 1;

    float acc[4][4][4];
#pragma unroll
    for (int i = 0; i < 4; i++)
#pragma unroll
        for (int j = 0; j < 4; j++)
#pragma unroll
            for (int k = 0; k < 4; k++) acc[i][j][k] = 0.0f;

    // stage s: kx = s>>2, cic = (s&3)*64
    auto stage_load = [&](int s) {
        const uint32_t base = sb + (uint32_t)(s & 1) * STAGE_BYTES;
        const int kx  = s >> 2;
        const int cic = (s & 3) << 6;
        const __half* ap = (kx == 0) ? ap0 : (kx == 1) ? ap1 : ap2;
        for (int i = tid; i < 5120; i += 256) {
            if (i < 3072) {                       // A: 3 taps x [128co][64ci]
                int ky  = i >> 10;
                int rem = i & 1023;
                int row = rem >> 3, g = rem & 7;
                const __half* src = gw + ((size_t)(b * 9 + ky * 3 + kx) * 256 +
                                          co0 + row) * 256 + cic + g * 8;
                CPA16(base + ky * 16384 + SWZ(row * 128 + g * 16), (const char*)src);
            } else {                              // B: 4 rows x [64ci][64px]
                int idx = i - 3072;
                int j = idx >> 9, r = (idx >> 3) & 63, g = idx & 7;
                const __half* src = ap + ((size_t)(b * 256 + cic + r) * PROW +
                                          (y0 + j)) * PCOLS + g * 8;
                CPA16(base + 49152 + j * 8192 + SWZ(r * 128 + g * 16), (const char*)src);
            }
        }
        asm volatile("cp.async.commit_group;" ::: "memory");
    };

    stage_load(0);
    stage_load(1);

    for (int s = 0; s < 12; s++) {
        if (s == 11) asm volatile("cp.async.wait_group 0;" ::: "memory");
        else         asm volatile("cp.async.wait_group 1;" ::: "memory");
        __syncthreads();

        const uint32_t base = sb + (uint32_t)(s & 1) * STAGE_BYTES;

#pragma unroll
        for (int ky = 0; ky < 3; ky++) {
            const uint32_t sA  = base + ky * 16384;
            const uint32_t sBj = base + 49152 + (jblk + ky) * 8192;

#pragma unroll
            for (int ki = 0; ki < 4; ki++) {
                uint32_t a[4][4];
#pragma unroll
                for (int mi = 0; mi < 4; mi++) {
                    uint32_t addr = sA + SWZ((wm * 64 + mi * 16 + lr) * 128 +
                                             ki * 32 + lhi * 16);
                    asm volatile("ldmatrix.sync.aligned.m8n8.x4.shared.b16 {%0,%1,%2,%3}, [%4];"
                                 : "=r"(a[mi][0]), "=r"(a[mi][1]), "=r"(a[mi][2]), "=r"(a[mi][3])
                                 : "r"(addr));
                }
                uint32_t bm[2][4];
#pragma unroll
                for (int nt = 0; nt < 2; nt++) {
                    uint32_t addr = sBj + SWZ((ki * 16 + lr) * 128 +
                                              (nbase + nt * 16 + lhi * 8) * 2);
                    asm volatile("ldmatrix.sync.aligned.m8n8.x4.trans.shared.b16 {%0,%1,%2,%3}, [%4];"
                                 : "=r"(bm[nt][0]), "=r"(bm[nt][1]), "=r"(bm[nt][2]), "=r"(bm[nt][3])
                                 : "r"(addr));
                }
#pragma unroll
                for (int mi = 0; mi < 4; mi++)
#pragma unroll
                    for (int ni = 0; ni < 4; ni++) {
                        uint32_t b0 = bm[ni >> 1][(ni & 1) * 2];
                        uint32_t b1 = bm[ni >> 1][(ni & 1) * 2 + 1];
                        asm volatile(
                            "mma.sync.aligned.m16n8k16.row.col.f32.f16.f16.f32 "
                            "{%0,%1,%2,%3}, {%4,%5,%6,%7}, {%8,%9}, {%0,%1,%2,%3};"
                            : "+f"(acc[mi][ni][0]), "+f"(acc[mi][ni][1]),
                              "+f"(acc[mi][ni][2]), "+f"(acc[mi][ni][3])
                            : "r"(a[mi][0]), "r"(a[mi][1]), "r"(a[mi][2]), "r"(a[mi][3]),
                              "r"(b0), "r"(b1));
                    }
            }
        }
        __syncthreads();                 // all warps done with buffer s&1
        if (s + 2 < 12) stage_load(s + 2);
    }

    // ---- epilogue: dump acc to SMEM [co][132] fp32, then coalesced stores --
    __syncthreads();
    float* sAcc = (float*)smem;
#pragma unroll
    for (int mi = 0; mi < 4; mi++)
#pragma unroll
        for (int h = 0; h < 2; h++) {
            const int co = wm * 64 + mi * 16 + (lane >> 2) + h * 8;
#pragma unroll
            for (int ni = 0; ni < 4; ni++) {
                const int px = wn * 32 + ni * 8 + (lane & 3) * 2;
                sAcc[co * 132 + px]     = acc[mi][ni][h * 2];
                sAcc[co * 132 + px + 1] = acc[mi][ni][h * 2 + 1];
            }
        }
    __syncthreads();

#pragma unroll
    for (int it = 0; it < 8; it++) {
        const int t2 = it * 256 + tid;
        const int co = t2 >> 4;            // 0..127
        const int ch = t2 & 15;
        const int j  = ch >> 3;            // row within 2-row tile
        const int xl = (ch & 7) * 8;       // x chunk base
        const float* rowp = sAcc + co * 132 + j * 64;
        float4 va = *(const float4*)(rowp + xl);
        float4 vb = *(const float4*)(rowp + xl + 4);
        const int coG = co0 + co;
        const int row = y0 + j;
        if (MODE == 0) {
            float vm1 = (xl == 0)  ? 0.0f : rowp[xl - 1];
            float vp8 = (xl == 56) ? 0.0f : rowp[xl + 8];
            float inv  = bn_g[coG] * rsqrtf(bn_v[coG] + 1e-5f);
            float bias = bn_b[coG] - bn_m[coG] * inv;
            float vv[10] = {vm1, va.x, va.y, va.z, va.w,
                            vb.x, vb.y, vb.z, vb.w, vp8};
            __half hh[10];
#pragma unroll
            for (int t = 0; t < 10; t++)
                hh[t] = __float2half(fmaxf(fmaf(vv[t], inv, bias), 0.0f));
            if (xl == 0)  hh[0] = __float2half(0.0f);
            if (xl == 56) hh[9] = __float2half(0.0f);
            const int rb = ((b * 256 + coG) * PROW + row + 1) * PCOLS + xl;
            *(uint4*)(o1 + rb) = pack8h(hh + 1);
            *(uint4*)(o0 + rb) = pack8h(hh + 0);
            *(uint4*)(o2 + rb) = pack8h(hh + 2);
        } else {
            const int gb = ((b * 256 + coG) << 12) + (row << 6) + xl;
            float4 x0 = *(const float4*)(xres + gb);
            float4 x1 = *(const float4*)(xres + gb + 4);
            float4 r0, r1;
            r0.x = va.x + x0.x; r0.y = va.y + x0.y;
            r0.z = va.z + x0.z; r0.w = va.w + x0.w;
            r1.x = vb.x + x1.x; r1.y = vb.y + x1.y;
            r1.z = vb.z + x1.z; r1.w = vb.w + x1.w;
            *(float4*)(out + gb)     = r0;
            *(float4*)(out + gb + 4) = r1;
        }
    }
}

// ------------------------------- launcher ----------------------------------
extern "C" void kernel_launch(void* const* d_in, const int* in_sizes, int n_in,
                              void* d_out, int out_size)
{
    const float* x    = (const float*)d_in[0];
    const float* h_in = (const float*)d_in[1];
    const float* g1   = (const float*)d_in[2];
    const float* be1  = (const float*)d_in[3];
    const float* m1   = (const float*)d_in[4];
    const float* v1   = (const float*)d_in[5];
    const float* w1   = (const float*)d_in[6];
    const float* b1   = (const float*)d_in[7];
    const float* g2   = (const float*)d_in[8];
    const float* be2  = (const float*)d_in[9];
    const float* m2   = (const float*)d_in[10];
    const float* v2   = (const float*)d_in[11];
    const float* w2   = (const float*)d_in[12];
    const float* b2   = (const float*)d_in[13];
    float* out = (float*)d_out;

    void *p1, *p2, *pg1, *pg2, *pw1, *pb1, *pw2, *pb2;
    cudaGetSymbolAddress(&p1, g_actp1);
    cudaGetSymbolAddress(&p2, g_actp2);
    cudaGetSymbolAddress(&pg1, g_gw1);
    cudaGetSymbolAddress(&pg2, g_gw2);
    cudaGetSymbolAddress(&pw1, g_wt1);
    cudaGetSymbolAddress(&pb1, g_bt1);
    cudaGetSymbolAddress(&pw2, g_wt2);
    cudaGetSymbolAddress(&pb2, g_bt2);
    __half* ap1 = (__half*)p1;
    __half* ap2 = (__half*)p2;
    __half* gw1 = (__half*)pg1;
    __half* gw2 = (__half*)pg2;

    cudaFuncSetAttribute(conv_mma<0>, cudaFuncAttributeMaxDynamicSharedMemorySize, SMEM_BYTES);
    cudaFuncSetAttribute(conv_mma<1>, cudaFuncAttributeMaxDynamicSharedMemorySize, SMEM_BYTES);

    wprep<<<(WSZ + 255) / 256, 256>>>(w1, b1, (float*)pw1, (float*)pb1);
    wprep<<<(WSZ + 255) / 256, 256>>>(w2, b2, (float*)pw2, (float*)pb2);
    wcombine<<<GWSZ / 8 / 256, 256>>>((const float*)pw1, (const float*)pb1, h_in, gw1);
    wcombine<<<GWSZ / 8 / 256, 256>>>((const float*)pw2, (const float*)pb2, h_in, gw2);
    zero_borders<<<(3 * NB * NC + 255) / 256, 256>>>(ap1);
    zero_borders<<<(3 * NB * NC + 255) / 256, 256>>>(ap2);
    bn_relu_pad<<<(NB * NC * 64 * 8) / 256, 256>>>(x, g1, be1, m1, v1,
                                                   ap1, ap1 + PSZ, ap1 + 2 * (size_t)PSZ);

    dim3 cg(32, 2, NB);
    conv_mma<0><<<cg, 256, SMEM_BYTES>>>(ap1, ap1 + PSZ, ap1 + 2 * (size_t)PSZ, gw1,
                                         g2, be2, m2, v2, nullptr,
                                         ap2, ap2 + PSZ, ap2 + 2 * (size_t)PSZ, nullptr);
    conv_mma<1><<<cg, 256, SMEM_BYTES>>>(ap2, ap2 + PSZ, ap2 + 2 * (size_t)PSZ, gw2,
                                         nullptr, nullptr, nullptr, nullptr, x,
                                         nullptr, nullptr, nullptr, out);
}

// round 9
// speedup vs baseline: 1.1319x; 1.1319x over previous
#include <cuda_runtime.h>
#include <cuda_fp16.h>
#include <cstdint>

// ---------------------------------------------------------------------------
// WideHyperBasicBlock via mma.sync (HMMA). conv3x3 = 9 shifted GEMMs,
// fp16 in / fp32 accum. act padded [b][c][66][72] fp16, 3 x-shifted copies.
// weights: fused per-sample combine h_b*W+Bw -> fp16 [b][tap][co][ci] (wgen).
// Conv CTA (R7 geometry): 128co x 128px (2 rows), 256 thr, 8 warps,
// warp = 64co x 32px; 3 SMEM buffers x 32KB, 1 sync/stage, hoisted prefetch.
// Epilogue via SMEM transpose -> coalesced uint4/float4 stores.
// ---------------------------------------------------------------------------

#define NB 32
#define NC 256
#define PROW 66
#define PCOLS 72
#define PSZ (NB * NC * PROW * PCOLS)
#define GWSZ (NB * 9 * NC * NC)

__device__ __half g_actp1[3][PSZ];
__device__ __half g_actp2[3][PSZ];
__device__ __half g_gw1[GWSZ];
__device__ __half g_gw2[GWSZ];

__device__ __forceinline__ uint32_t smem_u32(const void* p) {
    uint32_t a;
    asm("{ .reg .u64 t; cvta.to.shared.u64 t, %1; cvt.u32.u64 %0, t; }"
        : "=r"(a) : "l"(p));
    return a;
}
#define SWZ(o) ((o) ^ (((o) >> 3) & 0x70))
#define CPA16(dst, src) \
    asm volatile("cp.async.cg.shared.global [%0], [%1], 16;" :: "r"(dst), "l"(src) : "memory")

__device__ __forceinline__ uint4 pack8h(const __half* h) {
    union { uint4 u; __half2 h2[4]; } r;
    r.h2[0] = __halves2half2(h[0], h[1]);
    r.h2[1] = __halves2half2(h[2], h[3]);
    r.h2[2] = __halves2half2(h[4], h[5]);
    r.h2[3] = __halves2half2(h[6], h[7]);
    return r.u;
}

// --------------------------- aux kernels -----------------------------------
// zero halo borders of BOTH padded activation buffers in one launch
__global__ void zero_borders(__half* buf1, __half* buf2) {
    int t = blockIdx.x * blockDim.x + threadIdx.x;
    if (t >= 2 * 3 * NB * NC) return;
    __half* buf = (t < 3 * NB * NC) ? buf1 : buf2;
    int tt = t % (3 * NB * NC);
    int copy = tt / (NB * NC);
    int bc   = tt % (NB * NC);
    __half* base = buf + (size_t)copy * PSZ + (size_t)bc * PROW * PCOLS;
    uint4 z = {0, 0, 0, 0};
#pragma unroll
    for (int g = 0; g < 9; g++) {
        ((uint4*)(base))[g] = z;
        ((uint4*)(base + 65 * PCOLS))[g] = z;
    }
    __half hz = __float2half(0.0f);
    if (copy == 0) for (int r = 1; r < 65; r++) base[r * PCOLS] = hz;
    if (copy == 2) for (int r = 1; r < 65; r++) base[r * PCOLS + 63] = hz;
}

// fused weight-gen: gather w/bw once (stride-9), write all 32 samples.
// gw[b][k][co][ci] = fp16(h_b * w + bw),  h_b = 0.5 + hv[b]/64
__global__ void wgen(const float* __restrict__ w, const float* __restrict__ bw,
                     const float* __restrict__ hv, __half* __restrict__ gw) {
    int gid = blockIdx.x * blockDim.x + threadIdx.x;   // [k][m/2]
    int k = gid >> 15;          // 0..8
    int j = gid & 32767;
    int m = j * 2;              // co*256+ci, even
    float w0 = w[m * 9 + k],      w1 = w[(m + 1) * 9 + k];
    float b0 = bw[m * 9 + k],     b1 = bw[(m + 1) * 9 + k];
    __half* dst = gw + (k << 16) + m;
#pragma unroll 4
    for (int b = 0; b < 32; b++) {
        float h = 0.5f + hv[b] * (1.0f / 64.0f);
        __half2 r = __floats2half2_rn(fmaf(h, w0, b0), fmaf(h, w1, b1));
        *(__half2*)(dst + (size_t)b * (9 * 65536)) = r;
    }
}

// bn+relu+pad, 8 px per thread, all three copies via aligned uint4 stores
__global__ void bn_relu_pad(const float* __restrict__ x,
                            const float* __restrict__ g, const float* __restrict__ be,
                            const float* __restrict__ m, const float* __restrict__ v,
                            __half* __restrict__ a0, __half* __restrict__ a1,
                            __half* __restrict__ a2) {
    int gid = blockIdx.x * blockDim.x + threadIdx.x;    // [b][c][yy][xc]
    int xc = gid & 7, yy = (gid >> 3) & 63, c = (gid >> 9) & 255, b = gid >> 17;
    float inv  = g[c] * rsqrtf(v[c] + 1e-5f);
    float bias = be[c] - m[c] * inv;
    const float* xp = x + (((size_t)(b * 256 + c)) << 12) + (yy << 6) + xc * 8;
    float4 va = *(const float4*)xp;
    float4 vb = *(const float4*)(xp + 4);
    float vv[10];
    vv[0] = (xc == 0) ? 0.0f : xp[-1];
    vv[1] = va.x; vv[2] = va.y; vv[3] = va.z; vv[4] = va.w;
    vv[5] = vb.x; vv[6] = vb.y; vv[7] = vb.z; vv[8] = vb.w;
    vv[9] = (xc == 7) ? 0.0f : xp[8];
    __half hh[10];
#pragma unroll
    for (int t = 0; t < 10; t++)
        hh[t] = __float2half(fmaxf(fmaf(vv[t], inv, bias), 0.0f));
    if (xc == 0) hh[0] = __float2half(0.0f);
    if (xc == 7) hh[9] = __float2half(0.0f);
    int rb = ((b * 256 + c) * PROW + yy + 1) * PCOLS + xc * 8;
    *(uint4*)(a1 + rb) = pack8h(hh + 1);
    *(uint4*)(a0 + rb) = pack8h(hh + 0);
    *(uint4*)(a2 + rb) = pack8h(hh + 2);
}

// --------------------------- main conv kernel ------------------------------
// CTA: 128 co x 128 px (2 rows). 256 threads, 8 warps: warp = 64co x 32px.
// 36 K-stages (9 taps x 4 ci-chunks of 64). 3 buffers x 32KB, 1 sync/stage.
#define STAGE_BYTES 32768
#define SMEM_BYTES  (3 * STAGE_BYTES)

template <int MODE>
__global__ __launch_bounds__(256, 2)
void conv_mma(const __half* __restrict__ ap0, const __half* __restrict__ ap1,
              const __half* __restrict__ ap2, const __half* __restrict__ gw,
              const float* __restrict__ bn_g, const float* __restrict__ bn_b,
              const float* __restrict__ bn_m, const float* __restrict__ bn_v,
              const float* __restrict__ xres,
              __half* __restrict__ o0, __half* __restrict__ o1, __half* __restrict__ o2,
              float* __restrict__ out)
{
    extern __shared__ __align__(1024) char smem[];
    const uint32_t sb = smem_u32(smem);
    const int tid  = threadIdx.x;
    const int wid  = tid >> 5, lane = tid & 31;
    const int wm   = wid & 1;          // co half (64 co)
    const int wn   = wid >> 1;         // 0..3: 32-px strip
    const int jblk = wn >> 1;          // which 64-px B block
    const int nbase = (wn & 1) * 32;

    const int y0  = blockIdx.x * 2;
    const int co0 = blockIdx.y * 128;
    const int b   = blockIdx.z;

    const int lr  = lane & 15;
    const int lhi = (lane >> 4) & 1;

    float acc[4][4][4];
#pragma unroll
    for (int i = 0; i < 4; i++)
#pragma unroll
        for (int j = 0; j < 4; j++)
#pragma unroll
            for (int k = 0; k < 4; k++) acc[i][j][k] = 0.0f;

    auto stage_load = [&](int s) {
        const uint32_t base = sb + (uint32_t)(s % 3) * STAGE_BYTES;
        const int tap = s >> 2;
        const int cic = (s & 3) << 6;
        const int ky  = tap / 3;
        const int kx  = tap - ky * 3;
        const __half* ap = (kx == 0) ? ap0 : (kx == 1) ? ap1 : ap2;
        const __half* gsrcA = gw + ((size_t)(b * 9 + tap) * 256 + co0) * 256 + cic;
        for (int i = tid; i < 2048; i += 256) {
            if (i < 1024) {                       // A: [128 co][64 ci]
                int row = i >> 3, g = i & 7;
                CPA16(base + SWZ(row * 128 + g * 16),
                      (const char*)(gsrcA + row * 256) + g * 16);
            } else {                              // B: 2 blk x [64 ci][64 px]
                int idx = i - 1024;
                int j = idx >> 9, r = (idx >> 3) & 63, g = idx & 7;
                CPA16(base + 16384 + j * 8192 + SWZ(r * 128 + g * 16),
                      (const char*)(ap + ((size_t)(b * 256 + cic + r) * PROW +
                                          (y0 + j + ky)) * PCOLS) + g * 16);
            }
        }
        asm volatile("cp.async.commit_group;" ::: "memory");
    };

    stage_load(0);
    stage_load(1);

    for (int s = 0; s < 36; s++) {
        if (s == 35) asm volatile("cp.async.wait_group 0;" ::: "memory");
        else         asm volatile("cp.async.wait_group 1;" ::: "memory");
        __syncthreads();

        // hoisted prefetch: buffer (s+2)%3 == (s-1)%3, freed by the sync above
        if (s + 2 < 36) stage_load(s + 2);

        const uint32_t base = sb + (uint32_t)(s % 3) * STAGE_BYTES;
        const uint32_t sA  = base;
        const uint32_t sBj = base + 16384 + jblk * 8192;

#pragma unroll
        for (int ki = 0; ki < 4; ki++) {
            uint32_t a[4][4];
#pragma unroll
            for (int mi = 0; mi < 4; mi++) {
                uint32_t addr = sA + SWZ((wm * 64 + mi * 16 + lr) * 128 +
                                         ki * 32 + lhi * 16);
                asm volatile("ldmatrix.sync.aligned.m8n8.x4.shared.b16 {%0,%1,%2,%3}, [%4];"
                             : "=r"(a[mi][0]), "=r"(a[mi][1]), "=r"(a[mi][2]), "=r"(a[mi][3])
                             : "r"(addr));
            }
            uint32_t bm[2][4];
#pragma unroll
            for (int nt = 0; nt < 2; nt++) {
                uint32_t addr = sBj + SWZ((ki * 16 + lr) * 128 +
                                          (nbase + nt * 16 + lhi * 8) * 2);
                asm volatile("ldmatrix.sync.aligned.m8n8.x4.trans.shared.b16 {%0,%1,%2,%3}, [%4];"
                             : "=r"(bm[nt][0]), "=r"(bm[nt][1]), "=r"(bm[nt][2]), "=r"(bm[nt][3])
                             : "r"(addr));
            }
#pragma unroll
            for (int mi = 0; mi < 4; mi++)
#pragma unroll
                for (int ni = 0; ni < 4; ni++) {
                    uint32_t b0 = bm[ni >> 1][(ni & 1) * 2];
                    uint32_t b1 = bm[ni >> 1][(ni & 1) * 2 + 1];
                    asm volatile(
                        "mma.sync.aligned.m16n8k16.row.col.f32.f16.f16.f32 "
                        "{%0,%1,%2,%3}, {%4,%5,%6,%7}, {%8,%9}, {%0,%1,%2,%3};"
                        : "+f"(acc[mi][ni][0]), "+f"(acc[mi][ni][1]),
                          "+f"(acc[mi][ni][2]), "+f"(acc[mi][ni][3])
                        : "r"(a[mi][0]), "r"(a[mi][1]), "r"(a[mi][2]), "r"(a[mi][3]),
                          "r"(b0), "r"(b1));
                }
        }
    }

    // ---- epilogue: dump acc to SMEM [co][132] fp32, then coalesced stores --
    __syncthreads();
    float* sAcc = (float*)smem;
#pragma unroll
    for (int mi = 0; mi < 4; mi++)
#pragma unroll
        for (int h = 0; h < 2; h++) {
            const int co = wm * 64 + mi * 16 + (lane >> 2) + h * 8;
#pragma unroll
            for (int ni = 0; ni < 4; ni++) {
                const int px = wn * 32 + ni * 8 + (lane & 3) * 2;
                sAcc[co * 132 + px]     = acc[mi][ni][h * 2];
                sAcc[co * 132 + px + 1] = acc[mi][ni][h * 2 + 1];
            }
        }
    __syncthreads();

#pragma unroll
    for (int it = 0; it < 8; it++) {
        const int t2 = it * 256 + tid;
        const int co = t2 >> 4;            // 0..127
        const int ch = t2 & 15;
        const int j  = ch >> 3;            // row within 2-row tile
        const int xl = (ch & 7) * 8;       // x chunk base
        const float* rowp = sAcc + co * 132 + j * 64;
        float4 va = *(const float4*)(rowp + xl);
        float4 vb = *(const float4*)(rowp + xl + 4);
        const int coG = co0 + co;
        const int row = y0 + j;
        if (MODE == 0) {
            float vm1 = (xl == 0)  ? 0.0f : rowp[xl - 1];
            float vp8 = (xl == 56) ? 0.0f : rowp[xl + 8];
            float inv  = bn_g[coG] * rsqrtf(bn_v[coG] + 1e-5f);
            float bias = bn_b[coG] - bn_m[coG] * inv;
            float vv[10] = {vm1, va.x, va.y, va.z, va.w,
                            vb.x, vb.y, vb.z, vb.w, vp8};
            __half hh[10];
#pragma unroll
            for (int t = 0; t < 10; t++)
                hh[t] = __float2half(fmaxf(fmaf(vv[t], inv, bias), 0.0f));
            if (xl == 0)  hh[0] = __float2half(0.0f);
            if (xl == 56) hh[9] = __float2half(0.0f);
            const int rb = ((b * 256 + coG) * PROW + row + 1) * PCOLS + xl;
            *(uint4*)(o1 + rb) = pack8h(hh + 1);
            *(uint4*)(o0 + rb) = pack8h(hh + 0);
            *(uint4*)(o2 + rb) = pack8h(hh + 2);
        } else {
            const int gb = ((b * 256 + coG) << 12) + (row << 6) + xl;
            float4 x0 = *(const float4*)(xres + gb);
            float4 x1 = *(const float4*)(xres + gb + 4);
            float4 r0, r1;
            r0.x = va.x + x0.x; r0.y = va.y + x0.y;
            r0.z = va.z + x0.z; r0.w = va.w + x0.w;
            r1.x = vb.x + x1.x; r1.y = vb.y + x1.y;
            r1.z = vb.z + x1.z; r1.w = vb.w + x1.w;
            *(float4*)(out + gb)     = r0;
            *(float4*)(out + gb + 4) = r1;
        }
    }
}

// ------------------------------- launcher ----------------------------------
extern "C" void kernel_launch(void* const* d_in, const int* in_sizes, int n_in,
                              void* d_out, int out_size)
{
    const float* x    = (const float*)d_in[0];
    const float* h_in = (const float*)d_in[1];
    const float* g1   = (const float*)d_in[2];
    const float* be1  = (const float*)d_in[3];
    const float* m1   = (const float*)d_in[4];
    const float* v1   = (const float*)d_in[5];
    const float* w1   = (const float*)d_in[6];
    const float* b1   = (const float*)d_in[7];
    const float* g2   = (const float*)d_in[8];
    const float* be2  = (const float*)d_in[9];
    const float* m2   = (const float*)d_in[10];
    const float* v2   = (const float*)d_in[11];
    const float* w2   = (const float*)d_in[12];
    const float* b2   = (const float*)d_in[13];
    float* out = (float*)d_out;

    void *p1, *p2, *pg1, *pg2;
    cudaGetSymbolAddress(&p1, g_actp1);
    cudaGetSymbolAddress(&p2, g_actp2);
    cudaGetSymbolAddress(&pg1, g_gw1);
    cudaGetSymbolAddress(&pg2, g_gw2);
    __half* ap1 = (__half*)p1;
    __half* ap2 = (__half*)p2;
    __half* gw1 = (__half*)pg1;
    __half* gw2 = (__half*)pg2;

    cudaFuncSetAttribute(conv_mma<0>, cudaFuncAttributeMaxDynamicSharedMemorySize, SMEM_BYTES);
    cudaFuncSetAttribute(conv_mma<1>, cudaFuncAttributeMaxDynamicSharedMemorySize, SMEM_BYTES);

    wgen<<<(9 * 32768) / 256, 256>>>(w1, b1, h_in, gw1);
    wgen<<<(9 * 32768) / 256, 256>>>(w2, b2, h_in, gw2);
    zero_borders<<<(2 * 3 * NB * NC + 255) / 256, 256>>>(ap1, ap2);
    bn_relu_pad<<<(NB * NC * 64 * 8) / 256, 256>>>(x, g1, be1, m1, v1,
                                                   ap1, ap1 + PSZ, ap1 + 2 * (size_t)PSZ);

    dim3 cg(32, 2, NB);
    conv_mma<0><<<cg, 256, SMEM_BYTES>>>(ap1, ap1 + PSZ, ap1 + 2 * (size_t)PSZ, gw1,
                                         g2, be2, m2, v2, nullptr,
                                         ap2, ap2 + PSZ, ap2 + 2 * (size_t)PSZ, nullptr);
    conv_mma<1><<<cg, 256, SMEM_BYTES>>>(ap2, ap2 + PSZ, ap2 + 2 * (size_t)PSZ, gw2,
                                         nullptr, nullptr, nullptr, nullptr, x,
                                         nullptr, nullptr, nullptr, out);
}

// round 10
// speedup vs baseline: 1.3235x; 1.1693x over previous
#include <cuda_runtime.h>
#include <cuda_fp16.h>
#include <cstdint>

// ---------------------------------------------------------------------------
// WideHyperBasicBlock via mma.sync (HMMA). conv3x3 = 9 shifted GEMMs,
// fp16 in / fp32 accum.
// KEY CHANGE vs R9: activations stored channel-last actT[b][y][x][ci]
// (66x66 padded, 512B rows). x/y shifts are row offsets -> 16B-aligned,
// so ONE padded copy replaces the 3 x-shifted copies. B tiles are [px][ci]
// rows -> non-trans ldmatrix gives the col-major B fragment directly.
// Conv CTA: 128co x 128px (2 rows), 256 thr, 8 warps, warp = 64co x 32px;
// 3 SMEM buffers x 32KB, 1 sync/stage, hoisted prefetch.
// ---------------------------------------------------------------------------

#define NB 32
#define NC 256
#define YT 66
#define XT 66
#define ATSZ (NB * YT * XT * NC)     // 35,684,352 halfs (~71MB)
#define GWSZ (NB * 9 * NC * NC)

__device__ __half g_at1[ATSZ];
__device__ __half g_at2[ATSZ];
__device__ __half g_gw1[GWSZ];
__device__ __half g_gw2[GWSZ];

__device__ __forceinline__ uint32_t smem_u32(const void* p) {
    uint32_t a;
    asm("{ .reg .u64 t; cvta.to.shared.u64 t, %1; cvt.u32.u64 %0, t; }"
        : "=r"(a) : "l"(p));
    return a;
}
#define SWZ(o) ((o) ^ (((o) >> 3) & 0x70))
#define CPA16(dst, src) \
    asm volatile("cp.async.cg.shared.global [%0], [%1], 16;" :: "r"(dst), "l"(src) : "memory")

__device__ __forceinline__ uint4 pack8h(const __half* h) {
    union { uint4 u; __half2 h2[4]; } r;
    r.h2[0] = __halves2half2(h[0], h[1]);
    r.h2[1] = __halves2half2(h[2], h[3]);
    r.h2[2] = __halves2half2(h[4], h[5]);
    r.h2[3] = __halves2half2(h[6], h[7]);
    return r.u;
}

// --------------------------- aux kernels -----------------------------------
// zero halo borders (y=0,65 planes; x=0,65 columns) of both actT buffers.
// per buffer: 32 b x 8320 16B-chunks.
__global__ void zero_borders(__half* b1, __half* b2) {
    int gid = blockIdx.x * blockDim.x + threadIdx.x;
    const int per = 32 * 8320;
    if (gid >= 2 * per) return;
    __half* buf = (gid < per) ? b1 : b2;
    int r0 = gid % per;
    int b = r0 / 8320, r = r0 % 8320;
    int y, x, g;
    if (r < 4224) {                  // y planes: 2 x 66 x 32
        y = (r < 2112) ? 0 : 65;
        int rr = r % 2112;
        x = rr >> 5; g = rr & 31;
    } else {                         // x columns: 64 y x 2 x 32
        int rr = r - 4224;
        y = 1 + (rr >> 6);
        int rem = rr & 63;
        x = (rem < 32) ? 0 : 65; g = rem & 31;
    }
    uint4 z = {0, 0, 0, 0};
    *(uint4*)(buf + (((size_t)b * YT + y) * XT + x) * NC + g * 8) = z;
}

// fused weight-gen: gather w/bw once (stride-9), write all 32 samples.
__global__ void wgen(const float* __restrict__ w, const float* __restrict__ bw,
                     const float* __restrict__ hv, __half* __restrict__ gw) {
    int gid = blockIdx.x * blockDim.x + threadIdx.x;   // [k][m/2]
    int k = gid >> 15;
    int j = gid & 32767;
    int m = j * 2;
    float w0 = w[m * 9 + k],  w1 = w[(m + 1) * 9 + k];
    float b0 = bw[m * 9 + k], b1 = bw[(m + 1) * 9 + k];
    __half* dst = gw + (k << 16) + m;
#pragma unroll 4
    for (int b = 0; b < 32; b++) {
        float h = 0.5f + hv[b] * (1.0f / 64.0f);
        __half2 r = __floats2half2_rn(fmaf(h, w0, b0), fmaf(h, w1, b1));
        *(__half2*)(dst + (size_t)b * (9 * 65536)) = r;
    }
}

// bn+relu + transpose to channel-last actT[b][y+1][x+1][c] via SMEM.
// block = (y, b); 256 threads.
__global__ __launch_bounds__(256)
void bn_relu_pad_T(const float* __restrict__ x,
                   const float* __restrict__ g, const float* __restrict__ be,
                   const float* __restrict__ m, const float* __restrict__ v,
                   __half* __restrict__ at) {
    __shared__ __half sT[64 * 258];   // [x][c+pad]
    const int y = blockIdx.x, b = blockIdx.y;
    const int t = threadIdx.x;
    const int xcol = t & 63, cg = t >> 6;
#pragma unroll 4
    for (int i = 0; i < 64; i++) {
        int c = i * 4 + cg;
        float inv  = g[c] * rsqrtf(v[c] + 1e-5f);
        float bias = be[c] - m[c] * inv;
        float xv = x[(((size_t)(b * 256 + c)) << 12) + (y << 6) + xcol];
        sT[xcol * 258 + c] = __float2half(fmaxf(fmaf(xv, inv, bias), 0.0f));
    }
    __syncthreads();
#pragma unroll
    for (int it = 0; it < 8; it++) {
        int id = it * 256 + t;
        int xx = id >> 5, gg = id & 31;
        const uint32_t* sp = (const uint32_t*)(sT + xx * 258 + gg * 8);
        uint4 val = {sp[0], sp[1], sp[2], sp[3]};
        *(uint4*)(at + (((size_t)b * YT + y + 1) * XT + (xx + 1)) * NC + gg * 8) = val;
    }
}

// --------------------------- main conv kernel ------------------------------
// CTA: 128 co x 128 px (2 rows). 256 threads, 8 warps: warp = 64co x 32px.
// 36 K-stages (9 taps x 4 ci-chunks of 64). 3 buffers x 32KB, 1 sync/stage.
// Stage: A[128co x 64ci] @+0 ; B[2 rows][64px x 64ci] @+16384 (rows of 128B).
#define STAGE_BYTES 32768
#define SMEM_BYTES  (3 * STAGE_BYTES)

template <int MODE>
__global__ __launch_bounds__(256, 2)
void conv_mma(const __half* __restrict__ at, const __half* __restrict__ gw,
              const float* __restrict__ bn_g, const float* __restrict__ bn_b,
              const float* __restrict__ bn_m, const float* __restrict__ bn_v,
              const float* __restrict__ xres,
              __half* __restrict__ oT, float* __restrict__ out)
{
    extern __shared__ __align__(1024) char smem[];
    __shared__ float sSc[128], sBi[128];
    const uint32_t sb = smem_u32(smem);
    const int tid  = threadIdx.x;
    const int wid  = tid >> 5, lane = tid & 31;
    const int wm   = wid & 1;          // co half (64 co)
    const int wn   = wid >> 1;         // 0..3: 32-px strip
    const int jblk = wn >> 1;          // which 64-px B block (output row)
    const int nbase = (wn & 1) * 32;

    const int y0  = blockIdx.x * 2;
    const int co0 = blockIdx.y * 128;
    const int b   = blockIdx.z;

    const int lr  = lane & 15;
    const int lhi = (lane >> 4) & 1;

    if (MODE == 0 && tid < 128) {
        int co = co0 + tid;
        float inv = bn_g[co] * rsqrtf(bn_v[co] + 1e-5f);
        sSc[tid] = inv;
        sBi[tid] = bn_b[co] - bn_m[co] * inv;
    }

    float acc[4][4][4];
#pragma unroll
    for (int i = 0; i < 4; i++)
#pragma unroll
        for (int j = 0; j < 4; j++)
#pragma unroll
            for (int k = 0; k < 4; k++) acc[i][j][k] = 0.0f;

    auto stage_load = [&](int s) {
        const uint32_t base = sb + (uint32_t)(s % 3) * STAGE_BYTES;
        const int tap = s >> 2;
        const int cic = (s & 3) << 6;
        const int ky  = tap / 3;
        const int kx  = tap - ky * 3;
        const __half* gsrcA = gw + ((size_t)(b * 9 + tap) * 256 + co0) * 256 + cic;
        for (int i = tid; i < 2048; i += 256) {
            if (i < 1024) {                       // A: [128 co][64 ci]
                int row = i >> 3, g = i & 7;
                CPA16(base + SWZ(row * 128 + g * 16),
                      (const char*)(gsrcA + row * 256) + g * 16);
            } else {                              // B: 2 rows x [64 px][64 ci]
                int idx = i - 1024;
                int j = idx >> 9, r = (idx >> 3) & 63, g = idx & 7;
                const __half* src = at +
                    (((size_t)b * YT + (y0 + j + ky)) * XT + (r + kx)) * NC +
                    cic + g * 8;
                CPA16(base + 16384 + j * 8192 + SWZ(r * 128 + g * 16),
                      (const char*)src);
            }
        }
        asm volatile("cp.async.commit_group;" ::: "memory");
    };

    stage_load(0);
    stage_load(1);

    for (int s = 0; s < 36; s++) {
        if (s == 35) asm volatile("cp.async.wait_group 0;" ::: "memory");
        else         asm volatile("cp.async.wait_group 1;" ::: "memory");
        __syncthreads();

        if (s + 2 < 36) stage_load(s + 2);

        const uint32_t base = sb + (uint32_t)(s % 3) * STAGE_BYTES;
        const uint32_t sA  = base;
        const uint32_t sBj = base + 16384 + jblk * 8192;

#pragma unroll
        for (int ki = 0; ki < 4; ki++) {
            uint32_t a[4][4];
#pragma unroll
            for (int mi = 0; mi < 4; mi++) {
                uint32_t addr = sA + SWZ((wm * 64 + mi * 16 + lr) * 128 +
                                         ki * 32 + lhi * 16);
                asm volatile("ldmatrix.sync.aligned.m8n8.x4.shared.b16 {%0,%1,%2,%3}, [%4];"
                             : "=r"(a[mi][0]), "=r"(a[mi][1]), "=r"(a[mi][2]), "=r"(a[mi][3])
                             : "r"(addr));
            }
            uint32_t bm[2][4];
#pragma unroll
            for (int nt = 0; nt < 2; nt++) {
                // non-trans: rows = px, 16B k-halves selected by lane bit 3,
                // px+8 group by lane bit 4.
                uint32_t addr = sBj +
                    SWZ((nbase + nt * 16 + (lane & 7) + lhi * 8) * 128 +
                        ki * 32 + ((lane >> 3) & 1) * 16);
                asm volatile("ldmatrix.sync.aligned.m8n8.x4.shared.b16 {%0,%1,%2,%3}, [%4];"
                             : "=r"(bm[nt][0]), "=r"(bm[nt][1]), "=r"(bm[nt][2]), "=r"(bm[nt][3])
                             : "r"(addr));
            }
#pragma unroll
            for (int mi = 0; mi < 4; mi++)
#pragma unroll
                for (int ni = 0; ni < 4; ni++) {
                    uint32_t b0 = bm[ni >> 1][(ni & 1) * 2];
                    uint32_t b1 = bm[ni >> 1][(ni & 1) * 2 + 1];
                    asm volatile(
                        "mma.sync.aligned.m16n8k16.row.col.f32.f16.f16.f32 "
                        "{%0,%1,%2,%3}, {%4,%5,%6,%7}, {%8,%9}, {%0,%1,%2,%3};"
                        : "+f"(acc[mi][ni][0]), "+f"(acc[mi][ni][1]),
                          "+f"(acc[mi][ni][2]), "+f"(acc[mi][ni][3])
                        : "r"(a[mi][0]), "r"(a[mi][1]), "r"(a[mi][2]), "r"(a[mi][3]),
                          "r"(b0), "r"(b1));
                }
        }
    }

    __syncthreads();

    if (MODE == 0) {
        // transpose to [px][co(+pad 136)] then bn+relu -> channel-last oT
        float* sT = (float*)smem;
#pragma unroll
        for (int mi = 0; mi < 4; mi++)
#pragma unroll
            for (int h = 0; h < 2; h++) {
                const int co = wm * 64 + mi * 16 + (lane >> 2) + h * 8;
#pragma unroll
                for (int ni = 0; ni < 4; ni++) {
                    const int px = wn * 32 + ni * 8 + (lane & 3) * 2;
                    sT[px * 136 + co]       = acc[mi][ni][h * 2];
                    sT[(px + 1) * 136 + co] = acc[mi][ni][h * 2 + 1];
                }
            }
        __syncthreads();
#pragma unroll
        for (int it = 0; it < 8; it++) {
            const int id = it * 256 + tid;
            const int g = id & 15, xx = (id >> 4) & 63, j = id >> 10;
            const float* rp = sT + (j * 64 + xx) * 136 + g * 8;
            float4 va = *(const float4*)rp;
            float4 vb = *(const float4*)(rp + 4);
            float vv[8] = {va.x, va.y, va.z, va.w, vb.x, vb.y, vb.z, vb.w};
            __half hh[8];
#pragma unroll
            for (int i = 0; i < 8; i++)
                hh[i] = __float2half(
                    fmaxf(fmaf(vv[i], sSc[g * 8 + i], sBi[g * 8 + i]), 0.0f));
            *(uint4*)(oT + (((size_t)b * YT + (y0 + j + 1)) * XT + (xx + 1)) * NC +
                      co0 + g * 8) = pack8h(hh);
        }
    } else {
        // [co][px(+pad 132)] then residual add -> NCHW fp32 out
        float* sAcc = (float*)smem;
#pragma unroll
        for (int mi = 0; mi < 4; mi++)
#pragma unroll
            for (int h = 0; h < 2; h++) {
                const int co = wm * 64 + mi * 16 + (lane >> 2) + h * 8;
#pragma unroll
                for (int ni = 0; ni < 4; ni++) {
                    const int px = wn * 32 + ni * 8 + (lane & 3) * 2;
                    sAcc[co * 132 + px]     = acc[mi][ni][h * 2];
                    sAcc[co * 132 + px + 1] = acc[mi][ni][h * 2 + 1];
                }
            }
        __syncthreads();
#pragma unroll
        for (int it = 0; it < 8; it++) {
            const int t2 = it * 256 + tid;
            const int co = t2 >> 4;
            const int ch = t2 & 15;
            const int j  = ch >> 3;
            const int xl = (ch & 7) * 8;
            const float* rowp = sAcc + co * 132 + j * 64;
            float4 va = *(const float4*)(rowp + xl);
            float4 vb = *(const float4*)(rowp + xl + 4);
            const int gb = ((b * 256 + co0 + co) << 12) + ((y0 + j) << 6) + xl;
            float4 x0 = *(const float4*)(xres + gb);
            float4 x1 = *(const float4*)(xres + gb + 4);
            float4 r0, r1;
            r0.x = va.x + x0.x; r0.y = va.y + x0.y;
            r0.z = va.z + x0.z; r0.w = va.w + x0.w;
            r1.x = vb.x + x1.x; r1.y = vb.y + x1.y;
            r1.z = vb.z + x1.z; r1.w = vb.w + x1.w;
            *(float4*)(out + gb)     = r0;
            *(float4*)(out + gb + 4) = r1;
        }
    }
}

// ------------------------------- launcher ----------------------------------
extern "C" void kernel_launch(void* const* d_in, const int* in_sizes, int n_in,
                              void* d_out, int out_size)
{
    const float* x    = (const float*)d_in[0];
    const float* h_in = (const float*)d_in[1];
    const float* g1   = (const float*)d_in[2];
    const float* be1  = (const float*)d_in[3];
    const float* m1   = (const float*)d_in[4];
    const float* v1   = (const float*)d_in[5];
    const float* w1   = (const float*)d_in[6];
    const float* b1   = (const float*)d_in[7];
    const float* g2   = (const float*)d_in[8];
    const float* be2  = (const float*)d_in[9];
    const float* m2   = (const float*)d_in[10];
    const float* v2   = (const float*)d_in[11];
    const float* w2   = (const float*)d_in[12];
    const float* b2   = (const float*)d_in[13];
    float* out = (float*)d_out;

    void *p1, *p2, *pg1, *pg2;
    cudaGetSymbolAddress(&p1, g_at1);
    cudaGetSymbolAddress(&p2, g_at2);
    cudaGetSymbolAddress(&pg1, g_gw1);
    cudaGetSymbolAddress(&pg2, g_gw2);
    __half* at1 = (__half*)p1;
    __half* at2 = (__half*)p2;
    __half* gw1 = (__half*)pg1;
    __half* gw2 = (__half*)pg2;

    cudaFuncSetAttribute(conv_mma<0>, cudaFuncAttributeMaxDynamicSharedMemorySize, SMEM_BYTES);
    cudaFuncSetAttribute(conv_mma<1>, cudaFuncAttributeMaxDynamicSharedMemorySize, SMEM_BYTES);

    wgen<<<(9 * 32768) / 256, 256>>>(w1, b1, h_in, gw1);
    wgen<<<(9 * 32768) / 256, 256>>>(w2, b2, h_in, gw2);
    zero_borders<<<(2 * 32 * 8320 + 255) / 256, 256>>>(at1, at2);
    bn_relu_pad_T<<<dim3(64, 32), 256>>>(x, g1, be1, m1, v1, at1);

    dim3 cg(32, 2, NB);
    conv_mma<0><<<cg, 256, SMEM_BYTES>>>(at1, gw1, g2, be2, m2, v2,
                                         nullptr, at2, nullptr);
    conv_mma<1><<<cg, 256, SMEM_BYTES>>>(at2, gw2, nullptr, nullptr, nullptr, nullptr,
                                         x, nullptr, out);
}

// round 11
// speedup vs baseline: 1.5266x; 1.1534x over previous
#include <cuda_runtime.h>
#include <cuda_fp16.h>
#include <cstdint>

// ---------------------------------------------------------------------------
// WideHyperBasicBlock via mma.sync (HMMA). conv3x3 = 9 shifted GEMMs,
// fp16 in / fp32 accum. Activations channel-last actT[b][y][x][ci]
// (66x66 padded, 512B rows); shifts are row offsets -> one padded copy.
// R11: split staging cadence — B window (66 px rows) loaded once per
// (ky, ci-chunk) block and reused by all 3 kx taps (B traffic -65%).
// A-ring 3x16KB + B-ring 2x17KB = 82KB -> still 2 CTAs/SM.
// Conv CTA: 128co x 128px (2 rows), 256 thr, 8 warps, warp = 64co x 32px.
// ---------------------------------------------------------------------------

#define NB 32
#define NC 256
#define YT 66
#define XT 66
#define ATSZ (NB * YT * XT * NC)
#define GWSZ (NB * 9 * NC * NC)

__device__ __half g_at1[ATSZ];
__device__ __half g_at2[ATSZ];
__device__ __half g_gw1[GWSZ];
__device__ __half g_gw2[GWSZ];

__device__ __forceinline__ uint32_t smem_u32(const void* p) {
    uint32_t a;
    asm("{ .reg .u64 t; cvta.to.shared.u64 t, %1; cvt.u32.u64 %0, t; }"
        : "=r"(a) : "l"(p));
    return a;
}
#define SWZ(o) ((o) ^ (((o) >> 3) & 0x70))
#define CPA16(dst, src) \
    asm volatile("cp.async.cg.shared.global [%0], [%1], 16;" :: "r"(dst), "l"(src) : "memory")

__device__ __forceinline__ uint4 pack8h(const __half* h) {
    union { uint4 u; __half2 h2[4]; } r;
    r.h2[0] = __halves2half2(h[0], h[1]);
    r.h2[1] = __halves2half2(h[2], h[3]);
    r.h2[2] = __halves2half2(h[4], h[5]);
    r.h2[3] = __halves2half2(h[6], h[7]);
    return r.u;
}

// --------------------------- aux kernels -----------------------------------
__global__ void zero_borders(__half* b1, __half* b2) {
    int gid = blockIdx.x * blockDim.x + threadIdx.x;
    const int per = 32 * 8320;
    if (gid >= 2 * per) return;
    __half* buf = (gid < per) ? b1 : b2;
    int r0 = gid % per;
    int b = r0 / 8320, r = r0 % 8320;
    int y, x, g;
    if (r < 4224) {
        y = (r < 2112) ? 0 : 65;
        int rr = r % 2112;
        x = rr >> 5; g = rr & 31;
    } else {
        int rr = r - 4224;
        y = 1 + (rr >> 6);
        int rem = rr & 63;
        x = (rem < 32) ? 0 : 65; g = rem & 31;
    }
    uint4 z = {0, 0, 0, 0};
    *(uint4*)(buf + (((size_t)b * YT + y) * XT + x) * NC + g * 8) = z;
}

__global__ void wgen(const float* __restrict__ w, const float* __restrict__ bw,
                     const float* __restrict__ hv, __half* __restrict__ gw) {
    int gid = blockIdx.x * blockDim.x + threadIdx.x;
    int k = gid >> 15;
    int j = gid & 32767;
    int m = j * 2;
    float w0 = w[m * 9 + k],  w1 = w[(m + 1) * 9 + k];
    float b0 = bw[m * 9 + k], b1 = bw[(m + 1) * 9 + k];
    __half* dst = gw + (k << 16) + m;
#pragma unroll 4
    for (int b = 0; b < 32; b++) {
        float h = 0.5f + hv[b] * (1.0f / 64.0f);
        __half2 r = __floats2half2_rn(fmaf(h, w0, b0), fmaf(h, w1, b1));
        *(__half2*)(dst + (size_t)b * (9 * 65536)) = r;
    }
}

__global__ __launch_bounds__(256)
void bn_relu_pad_T(const float* __restrict__ x,
                   const float* __restrict__ g, const float* __restrict__ be,
                   const float* __restrict__ m, const float* __restrict__ v,
                   __half* __restrict__ at) {
    __shared__ __half sT[64 * 258];
    const int y = blockIdx.x, b = blockIdx.y;
    const int t = threadIdx.x;
    const int xcol = t & 63, cg = t >> 6;
#pragma unroll 4
    for (int i = 0; i < 64; i++) {
        int c = i * 4 + cg;
        float inv  = g[c] * rsqrtf(v[c] + 1e-5f);
        float bias = be[c] - m[c] * inv;
        float xv = x[(((size_t)(b * 256 + c)) << 12) + (y << 6) + xcol];
        sT[xcol * 258 + c] = __float2half(fmaxf(fmaf(xv, inv, bias), 0.0f));
    }
    __syncthreads();
#pragma unroll
    for (int it = 0; it < 8; it++) {
        int id = it * 256 + t;
        int xx = id >> 5, gg = id & 31;
        const uint32_t* sp = (const uint32_t*)(sT + xx * 258 + gg * 8);
        uint4 val = {sp[0], sp[1], sp[2], sp[3]};
        *(uint4*)(at + (((size_t)b * YT + y + 1) * XT + (xx + 1)) * NC + gg * 8) = val;
    }
}

// --------------------------- main conv kernel ------------------------------
// Stage s (0..35): block = s/3 (ky = block>>2, cic = (block&3)*64), kx = s%3.
// A ring: 3 x 16384 @ sb;  B ring: 2 x 17408 @ sb+49152
// B buffer: 2 output rows j, row px r (0..65) at j*8704 + SWZ(r*128+g*16).
#define A_RING   0
#define B_RING   49152
#define SMEM_BYTES 84992

template <int MODE>
__global__ __launch_bounds__(256, 2)
void conv_mma(const __half* __restrict__ at, const __half* __restrict__ gw,
              const float* __restrict__ bn_g, const float* __restrict__ bn_b,
              const float* __restrict__ bn_m, const float* __restrict__ bn_v,
              const float* __restrict__ xres,
              __half* __restrict__ oT, float* __restrict__ out)
{
    extern __shared__ __align__(1024) char smem[];
    __shared__ float sSc[128], sBi[128];
    const uint32_t sb = smem_u32(smem);
    const int tid  = threadIdx.x;
    const int wid  = tid >> 5, lane = tid & 31;
    const int wm   = wid & 1;
    const int wn   = wid >> 1;
    const int jblk = wn >> 1;
    const int nbase = (wn & 1) * 32;

    const int y0  = blockIdx.x * 2;
    const int co0 = blockIdx.y * 128;
    const int b   = blockIdx.z;

    const int lr  = lane & 15;
    const int lhi = (lane >> 4) & 1;

    if (MODE == 0 && tid < 128) {
        int co = co0 + tid;
        float inv = bn_g[co] * rsqrtf(bn_v[co] + 1e-5f);
        sSc[tid] = inv;
        sBi[tid] = bn_b[co] - bn_m[co] * inv;
    }

    float acc[4][4][4];
#pragma unroll
    for (int i = 0; i < 4; i++)
#pragma unroll
        for (int j = 0; j < 4; j++)
#pragma unroll
            for (int k = 0; k < 4; k++) acc[i][j][k] = 0.0f;

    // one commit per stage: A(s) (+ B(block) when s%3==0)
    auto load_stage = [&](int s) {
        const int blk = s / 3, kx = s % 3;
        const int ky  = blk >> 2;
        const int cic = (blk & 3) << 6;
        const int tap = ky * 3 + kx;
        const uint32_t aBase = sb + A_RING + (uint32_t)(s % 3) * 16384;
        const __half* gsrcA = gw + ((size_t)(b * 9 + tap) * 256 + co0) * 256 + cic;
#pragma unroll
        for (int i = tid; i < 1024; i += 256) {
            int row = i >> 3, g = i & 7;
            CPA16(aBase + SWZ(row * 128 + g * 16),
                  (const char*)(gsrcA + row * 256) + g * 16);
        }
        if (kx == 0) {                 // B block: 2 rows x 66 px x 64 ci
            const uint32_t bBase = sb + B_RING + (uint32_t)(blk & 1) * 17408;
            for (int i = tid; i < 1056; i += 256) {
                int j  = (i >= 528) ? 1 : 0;
                int r2 = i - j * 528;
                int r = r2 >> 3, g = r2 & 7;     // r = padded x, 0..65
                const __half* src = at +
                    (((size_t)b * YT + (y0 + j + ky)) * XT + r) * NC + cic + g * 8;
                CPA16(bBase + j * 8704 + SWZ(r * 128 + g * 16), (const char*)src);
            }
        }
        asm volatile("cp.async.commit_group;" ::: "memory");
    };

    load_stage(0);
    load_stage(1);

    for (int s = 0; s < 36; s++) {
        if (s == 35) asm volatile("cp.async.wait_group 0;" ::: "memory");
        else         asm volatile("cp.async.wait_group 1;" ::: "memory");
        __syncthreads();

        if (s + 2 < 36) load_stage(s + 2);

        const int blk = s / 3, kx = s % 3;
        const uint32_t sA  = sb + A_RING + (uint32_t)(s % 3) * 16384;
        const uint32_t sBj = sb + B_RING + (uint32_t)(blk & 1) * 17408 + jblk * 8704;

#pragma unroll
        for (int ki = 0; ki < 4; ki++) {
            uint32_t a[4][4];
#pragma unroll
            for (int mi = 0; mi < 4; mi++) {
                uint32_t addr = sA + SWZ((wm * 64 + mi * 16 + lr) * 128 +
                                         ki * 32 + lhi * 16);
                asm volatile("ldmatrix.sync.aligned.m8n8.x4.shared.b16 {%0,%1,%2,%3}, [%4];"
                             : "=r"(a[mi][0]), "=r"(a[mi][1]), "=r"(a[mi][2]), "=r"(a[mi][3])
                             : "r"(addr));
            }
            uint32_t bm[2][4];
#pragma unroll
            for (int nt = 0; nt < 2; nt++) {
                // non-trans ldmatrix; row = output px + kx
                uint32_t row = nbase + nt * 16 + (lane & 7) + lhi * 8 + kx;
                uint32_t addr = sBj + SWZ(row * 128 + ki * 32 + ((lane >> 3) & 1) * 16);
                asm volatile("ldmatrix.sync.aligned.m8n8.x4.shared.b16 {%0,%1,%2,%3}, [%4];"
                             : "=r"(bm[nt][0]), "=r"(bm[nt][1]), "=r"(bm[nt][2]), "=r"(bm[nt][3])
                             : "r"(addr));
            }
#pragma unroll
            for (int mi = 0; mi < 4; mi++)
#pragma unroll
                for (int ni = 0; ni < 4; ni++) {
                    uint32_t b0 = bm[ni >> 1][(ni & 1) * 2];
                    uint32_t b1 = bm[ni >> 1][(ni & 1) * 2 + 1];
                    asm volatile(
                        "mma.sync.aligned.m16n8k16.row.col.f32.f16.f16.f32 "
                        "{%0,%1,%2,%3}, {%4,%5,%6,%7}, {%8,%9}, {%0,%1,%2,%3};"
                        : "+f"(acc[mi][ni][0]), "+f"(acc[mi][ni][1]),
                          "+f"(acc[mi][ni][2]), "+f"(acc[mi][ni][3])
                        : "r"(a[mi][0]), "r"(a[mi][1]), "r"(a[mi][2]), "r"(a[mi][3]),
                          "r"(b0), "r"(b1));
                }
        }
    }

    __syncthreads();

    if (MODE == 0) {
        float* sT = (float*)smem;
#pragma unroll
        for (int mi = 0; mi < 4; mi++)
#pragma unroll
            for (int h = 0; h < 2; h++) {
                const int co = wm * 64 + mi * 16 + (lane >> 2) + h * 8;
#pragma unroll
                for (int ni = 0; ni < 4; ni++) {
                    const int px = wn * 32 + ni * 8 + (lane & 3) * 2;
                    sT[px * 136 + co]       = acc[mi][ni][h * 2];
                    sT[(px + 1) * 136 + co] = acc[mi][ni][h * 2 + 1];
                }
            }
        __syncthreads();
#pragma unroll
        for (int it = 0; it < 8; it++) {
            const int id = it * 256 + tid;
            const int g = id & 15, xx = (id >> 4) & 63, j = id >> 10;
            const float* rp = sT + (j * 64 + xx) * 136 + g * 8;
            float4 va = *(const float4*)rp;
            float4 vb = *(const float4*)(rp + 4);
            float vv[8] = {va.x, va.y, va.z, va.w, vb.x, vb.y, vb.z, vb.w};
            __half hh[8];
#pragma unroll
            for (int i = 0; i < 8; i++)
                hh[i] = __float2half(
                    fmaxf(fmaf(vv[i], sSc[g * 8 + i], sBi[g * 8 + i]), 0.0f));
            *(uint4*)(oT + (((size_t)b * YT + (y0 + j + 1)) * XT + (xx + 1)) * NC +
                      co0 + g * 8) = pack8h(hh);
        }
    } else {
        float* sAcc = (float*)smem;
#pragma unroll
        for (int mi = 0; mi < 4; mi++)
#pragma unroll
            for (int h = 0; h < 2; h++) {
                const int co = wm * 64 + mi * 16 + (lane >> 2) + h * 8;
#pragma unroll
                for (int ni = 0; ni < 4; ni++) {
                    const int px = wn * 32 + ni * 8 + (lane & 3) * 2;
                    sAcc[co * 132 + px]     = acc[mi][ni][h * 2];
                    sAcc[co * 132 + px + 1] = acc[mi][ni][h * 2 + 1];
                }
            }
        __syncthreads();
#pragma unroll
        for (int it = 0; it < 8; it++) {
            const int t2 = it * 256 + tid;
            const int co = t2 >> 4;
            const int ch = t2 & 15;
            const int j  = ch >> 3;
            const int xl = (ch & 7) * 8;
            const float* rowp = sAcc + co * 132 + j * 64;
            float4 va = *(const float4*)(rowp + xl);
            float4 vb = *(const float4*)(rowp + xl + 4);
            const int gb = ((b * 256 + co0 + co) << 12) + ((y0 + j) << 6) + xl;
            float4 x0 = *(const float4*)(xres + gb);
            float4 x1 = *(const float4*)(xres + gb + 4);
            float4 r0, r1;
            r0.x = va.x + x0.x; r0.y = va.y + x0.y;
            r0.z = va.z + x0.z; r0.w = va.w + x0.w;
            r1.x = vb.x + x1.x; r1.y = vb.y + x1.y;
            r1.z = vb.z + x1.z; r1.w = vb.w + x1.w;
            *(float4*)(out + gb)     = r0;
            *(float4*)(out + gb + 4) = r1;
        }
    }
}

// ------------------------------- launcher ----------------------------------
extern "C" void kernel_launch(void* const* d_in, const int* in_sizes, int n_in,
                              void* d_out, int out_size)
{
    const float* x    = (const float*)d_in[0];
    const float* h_in = (const float*)d_in[1];
    const float* g1   = (const float*)d_in[2];
    const float* be1  = (const float*)d_in[3];
    const float* m1   = (const float*)d_in[4];
    const float* v1   = (const float*)d_in[5];
    const float* w1   = (const float*)d_in[6];
    const float* b1   = (const float*)d_in[7];
    const float* g2   = (const float*)d_in[8];
    const float* be2  = (const float*)d_in[9];
    const float* m2   = (const float*)d_in[10];
    const float* v2   = (const float*)d_in[11];
    const float* w2   = (const float*)d_in[12];
    const float* b2   = (const float*)d_in[13];
    float* out = (float*)d_out;

    void *p1, *p2, *pg1, *pg2;
    cudaGetSymbolAddress(&p1, g_at1);
    cudaGetSymbolAddress(&p2, g_at2);
    cudaGetSymbolAddress(&pg1, g_gw1);
    cudaGetSymbolAddress(&pg2, g_gw2);
    __half* at1 = (__half*)p1;
    __half* at2 = (__half*)p2;
    __half* gw1 = (__half*)pg1;
    __half* gw2 = (__half*)pg2;

    cudaFuncSetAttribute(conv_mma<0>, cudaFuncAttributeMaxDynamicSharedMemorySize, SMEM_BYTES);
    cudaFuncSetAttribute(conv_mma<1>, cudaFuncAttributeMaxDynamicSharedMemorySize, SMEM_BYTES);

    wgen<<<(9 * 32768) / 256, 256>>>(w1, b1, h_in, gw1);
    wgen<<<(9 * 32768) / 256, 256>>>(w2, b2, h_in, gw2);
    zero_borders<<<(2 * 32 * 8320 + 255) / 256, 256>>>(at1, at2);
    bn_relu_pad_T<<<dim3(64, 32), 256>>>(x, g1, be1, m1, v1, at1);

    dim3 cg(32, 2, NB);
    conv_mma<0><<<cg, 256, SMEM_BYTES>>>(at1, gw1, g2, be2, m2, v2,
                                         nullptr, at2, nullptr);
    conv_mma<1><<<cg, 256, SMEM_BYTES>>>(at2, gw2, nullptr, nullptr, nullptr, nullptr,
                                         x, nullptr, out);
}